// round 16
// baseline (speedup 1.0000x reference)
#include <cuda_runtime.h>
#include <math.h>
#include <stdint.h>
#include <mma.h>
using namespace nvcuda;

// ---------------- constants ----------------
#define D     512
#define NH    8
#define DK    64
#define BSZ   16
#define TTRG  64
#define TT    64
#define SSP   49
#define DFF   2048
#define NT    1024
#define NV    50176
#define NBIG  65536

// ---------------- scratch (branch A + shared) ----------------
__device__ float g_bigKV[(size_t)2 * NV * D];   // K4,V4
__device__ float g_big2[(size_t)NV * D];        // O4
__device__ float g_qkv[(size_t)6144 * D];
__device__ float g_kvEnc[(size_t)7168 * D];
__device__ float g_ln [(size_t)NT * D];
__device__ float g_o  [(size_t)NT * D];
__device__ float g_cur[(size_t)NT * D];
__device__ float g_ts [(size_t)NT * D];
__device__ float g_mid[(size_t)NT * DFF];
__device__ float g_mmb[(size_t)NT * D];
__device__ float g_mmkv[(size_t)2 * NT * D];
__device__ float g_sb [(size_t)NT * NH];
__device__ float g_qo [(size_t)NT * NH * D];
__device__ float g_ctx[(size_t)NT * NH * D];
__device__ float g_w12[(size_t)2 * D * D];
__device__ float g_w1t[(size_t)D * D];
// ---------------- scratch (branch B private) ----------------
__device__ float g_bigKV2[(size_t)2 * NV * D];  // K6,V6
__device__ float g_big3[(size_t)NBIG * D];      // O6
__device__ float g_lnB [(size_t)NT * D];
__device__ float g_qB  [(size_t)NT * D];
__device__ float g_oB  [(size_t)NT * D];
__device__ float g_st  [(size_t)NT * D];
__device__ float g_midB[(size_t)NT * DFF];
__device__ float g_mmbB[(size_t)NT * D];
__device__ float g_mmkvB[(size_t)2 * NT * D];
__device__ float g_sbB [(size_t)NT * NH];
__device__ float g_qoB [(size_t)NT * NH * D];
__device__ float g_ctxB[(size_t)NT * NH * D];
__device__ float g_w12B[(size_t)2 * D * D];
__device__ float g_w1tB[(size_t)D * D];
// ---------------- tf32 pre-rounded inputs ----------
__device__ float g_vftR[(size_t)NV * D];
__device__ float g_wR  [(size_t)4 * D * D];

// ---------------- cp.async helpers ----------------
__device__ __forceinline__ void cp_async16(float* smem_dst, const float* gsrc) {
    uint32_t s = (uint32_t)__cvta_generic_to_shared(smem_dst);
    asm volatile("cp.async.cg.shared.global [%0], [%1], 16;\n" :: "r"(s), "l"(gsrc));
}
#define CP_COMMIT() asm volatile("cp.async.commit_group;\n" ::: "memory")
#define CP_WAIT(n)  asm volatile("cp.async.wait_group %0;\n" :: "n"(n) : "memory")

// ---------------- tf32 rounding kernel ----------------
__global__ void round_tf32_kernel(const float* __restrict__ in, float* __restrict__ out, long n4)
{
    long i = (long)blockIdx.x*256 + threadIdx.x;
    if (i < n4) {
        float4 v = ((const float4*)in)[i];
        v.x = wmma::__float_to_tf32(v.x);
        v.y = wmma::__float_to_tf32(v.y);
        v.z = wmma::__float_to_tf32(v.z);
        v.w = wmma::__float_to_tf32(v.w);
        ((float4*)out)[i] = v;
    }
}

// ============ big GEMM body: 3-stage pipeline, ONE sync per iteration ============
#define BIGBUF 8832
#define BIG_GEMM_BODY(CONV)                                                          \
    extern __shared__ float sm[];                                                    \
    const long z = blockIdx.z;                                                       \
    A += z*aStep; W += z*wStep;                                                      \
    const float* biasz = bias ? bias + z*bStep : nullptr;                            \
    const float* resz  = res  ? res  + z*rStep : nullptr;                            \
    float* Cz = C + z*cStep;                                                         \
    const int tid = threadIdx.x;                                                     \
    const int wid = tid >> 5;                                                        \
    const int wm = wid >> 1;                                                         \
    const int wn = wid & 1;                                                          \
    const int bm = blockIdx.y * 128;                                                 \
    const int bn = blockIdx.x * 128;                                                 \
    wmma::fragment<wmma::accumulator, 16,16,8, float> c[2][4];                       \
    _Pragma("unroll")                                                                \
    for (int i=0;i<2;i++)                                                            \
        _Pragma("unroll")                                                            \
        for (int j=0;j<4;j++) wmma::fill_fragment(c[i][j], 0.f);                     \
    const int nK = K >> 5;                                                           \
    auto issue = [&](int buf, int k0) {                                              \
        float* As = sm + buf*BIGBUF;                                                 \
        float* Bs = As + 128*36;                                                     \
        _Pragma("unroll")                                                            \
        for (int t=0;t<4;t++) {                                                      \
            int idx = tid + t*256;                                                   \
            int row = idx >> 3, q = idx & 7;                                         \
            cp_async16(&As[row*36 + q*4], A + (size_t)(bm+row)*lda + k0 + q*4);      \
        }                                                                            \
        _Pragma("unroll")                                                            \
        for (int t=0;t<4;t++) {                                                      \
            int idx = tid + t*256;                                                   \
            int row = idx >> 5, q = idx & 31;                                        \
            cp_async16(&Bs[row*132 + q*4], W + (size_t)(k0+row)*ldb + bn + q*4);     \
        }                                                                            \
        CP_COMMIT();                                                                 \
    };                                                                               \
    issue(0, 0);                                                                     \
    if (nK > 1) issue(1, 32);                                                        \
    for (int kt = 0; kt < nK; kt++) {                                                \
        if (kt+1 < nK) { CP_WAIT(1); } else { CP_WAIT(0); }                          \
        __syncthreads();                                                             \
        if (kt+2 < nK) issue((kt+2)%3, (kt+2)<<5);                                   \
        float* As = sm + (kt%3)*BIGBUF;                                              \
        float* Bs = As + 128*36;                                                     \
        _Pragma("unroll")                                                            \
        for (int ks=0; ks<4; ks++) {                                                 \
            wmma::fragment<wmma::matrix_a, 16,16,8, wmma::precision::tf32, wmma::row_major> a[2]; \
            wmma::fragment<wmma::matrix_b, 16,16,8, wmma::precision::tf32, wmma::row_major> b[4]; \
            _Pragma("unroll")                                                        \
            for (int i=0;i<2;i++) {                                                  \
                wmma::load_matrix_sync(a[i], &As[(wm*32 + i*16)*36 + ks*8], 36);     \
                if (CONV) {                                                          \
                    _Pragma("unroll")                                                \
                    for (int e=0;e<a[i].num_elements;e++)                            \
                        a[i].x[e] = wmma::__float_to_tf32(a[i].x[e]);                \
                }                                                                    \
            }                                                                        \
            _Pragma("unroll")                                                        \
            for (int j=0;j<4;j++) {                                                  \
                wmma::load_matrix_sync(b[j], &Bs[(ks*8)*132 + wn*64 + j*16], 132);   \
                if (CONV) {                                                          \
                    _Pragma("unroll")                                                \
                    for (int e=0;e<b[j].num_elements;e++)                            \
                        b[j].x[e] = wmma::__float_to_tf32(b[j].x[e]);                \
                }                                                                    \
            }                                                                        \
            _Pragma("unroll")                                                        \
            for (int i=0;i<2;i++)                                                    \
                _Pragma("unroll")                                                    \
                for (int j=0;j<4;j++)                                                \
                    wmma::mma_sync(c[i][j], a[i], b[j], c[i][j]);                    \
        }                                                                            \
    }                                                                                \
    __syncthreads();                                                                 \
    float* Cs = sm;                                                                  \
    _Pragma("unroll")                                                                \
    for (int i=0;i<2;i++)                                                            \
        _Pragma("unroll")                                                            \
        for (int j=0;j<4;j++)                                                        \
            wmma::store_matrix_sync(&Cs[(wm*32+i*16)*132 + wn*64 + j*16], c[i][j], 132, wmma::mem_row_major); \
    __syncthreads();                                                                 \
    _Pragma("unroll")                                                                \
    for (int t=0;t<16;t++) {                                                         \
        int idx = tid + t*256;                                                       \
        int row = idx >> 5, q = idx & 31;                                            \
        float4 v = *(float4*)&Cs[row*132 + q*4];                                     \
        if (biasz) {                                                                 \
            float4 bv = *(const float4*)(biasz + bn + q*4);                          \
            v.x += bv.x; v.y += bv.y; v.z += bv.z; v.w += bv.w;                      \
        }                                                                            \
        if (resz) {                                                                  \
            float4 rv = *(const float4*)(resz + (size_t)(bm+row)*ldres + bn + q*4);  \
            v.x += rv.x; v.y += rv.y; v.z += rv.z; v.w += rv.w;                      \
        }                                                                            \
        if (relu) {                                                                  \
            v.x = fmaxf(v.x,0.f); v.y = fmaxf(v.y,0.f);                              \
            v.z = fmaxf(v.z,0.f); v.w = fmaxf(v.w,0.f);                              \
        }                                                                            \
        *(float4*)(Cz + (size_t)(bm+row)*ldc + bn + q*4) = v;                        \
    }

__global__ void __launch_bounds__(256, 2)
tf32_gemm_big_b(int M, int N, int K,
                const float* __restrict__ A, int lda, long aStep,
                const float* __restrict__ W, int ldb, long wStep,
                const float* __restrict__ bias, long bStep,
                const float* res, int ldres, long rStep, int relu,
                float* __restrict__ C, int ldc, long cStep)
{
    BIG_GEMM_BODY(1)
}

__global__ void __launch_bounds__(256, 2)
tf32_gemm_bignc(int M, int N, int K,
                const float* __restrict__ A, int lda, long aStep,
                const float* __restrict__ W, int ldb, long wStep,
                const float* __restrict__ bias, long bStep,
                const float* res, int ldres, long rStep, int relu,
                float* __restrict__ C, int ldc, long cStep)
{
    BIG_GEMM_BODY(0)
}

// ======= small GEMM: 64x64x32, 4 warps, 3-stage, one sync/iter =======
#define SMBUF 4480
__global__ void tf32_gemm_small_b(int M, int N, int K,
                                  const float* __restrict__ A, int lda, long aStep,
                                  const float* __restrict__ W, int ldb, long wStep,
                                  const float* __restrict__ bias, long bStep,
                                  const float* res, int ldres, long rStep, int relu,
                                  float* __restrict__ C, int ldc, long cStep)
{
    extern __shared__ float sm[];       // 3*SMBUF floats (dynamic)
    const long z = blockIdx.z;
    A += z*aStep; W += z*wStep;
    const float* biasz = bias ? bias + z*bStep : nullptr;
    const float* resz  = res  ? res  + z*rStep : nullptr;
    float* Cz = C + z*cStep;

    const int tid = threadIdx.x;
    const int wid = tid >> 5;
    const int wm = wid >> 1;
    const int wn = wid & 1;
    const int bm = blockIdx.y * 64;
    const int bn = blockIdx.x * 64;

    wmma::fragment<wmma::accumulator, 16,16,8, float> c[2][2];
    #pragma unroll
    for (int i=0;i<2;i++)
        #pragma unroll
        for (int j=0;j<2;j++) wmma::fill_fragment(c[i][j], 0.f);

    const int nK = K >> 5;

    auto issue = [&](int buf, int k0) {
        float* As = sm + buf*SMBUF;
        float* Bs = As + 64*36;
        #pragma unroll
        for (int t=0;t<4;t++) {
            int idx = tid + t*128;
            int row = idx >> 3, q = idx & 7;
            cp_async16(&As[row*36 + q*4], A + (size_t)(bm+row)*lda + k0 + q*4);
        }
        #pragma unroll
        for (int t=0;t<4;t++) {
            int idx = tid + t*128;
            int row = idx >> 4, q = idx & 15;
            cp_async16(&Bs[row*68 + q*4], W + (size_t)(k0+row)*ldb + bn + q*4);
        }
        CP_COMMIT();
    };

    issue(0, 0);
    if (nK > 1) issue(1, 32);
    for (int kt = 0; kt < nK; kt++) {
        if (kt+1 < nK) { CP_WAIT(1); } else { CP_WAIT(0); }
        __syncthreads();
        if (kt+2 < nK) issue((kt+2)%3, (kt+2)<<5);
        float* As = sm + (kt%3)*SMBUF;
        float* Bs = As + 64*36;
        #pragma unroll
        for (int ks=0; ks<4; ks++) {
            wmma::fragment<wmma::matrix_a, 16,16,8, wmma::precision::tf32, wmma::row_major> a[2];
            wmma::fragment<wmma::matrix_b, 16,16,8, wmma::precision::tf32, wmma::row_major> b[2];
            #pragma unroll
            for (int i=0;i<2;i++) {
                wmma::load_matrix_sync(a[i], &As[(wm*32 + i*16)*36 + ks*8], 36);
                #pragma unroll
                for (int e=0;e<a[i].num_elements;e++) a[i].x[e] = wmma::__float_to_tf32(a[i].x[e]);
            }
            #pragma unroll
            for (int j=0;j<2;j++) {
                wmma::load_matrix_sync(b[j], &Bs[(ks*8)*68 + wn*32 + j*16], 68);
                #pragma unroll
                for (int e=0;e<b[j].num_elements;e++) b[j].x[e] = wmma::__float_to_tf32(b[j].x[e]);
            }
            #pragma unroll
            for (int i=0;i<2;i++)
                #pragma unroll
                for (int j=0;j<2;j++)
                    wmma::mma_sync(c[i][j], a[i], b[j], c[i][j]);
        }
    }
    __syncthreads();

    float* Cs = sm;
    #pragma unroll
    for (int i=0;i<2;i++)
        #pragma unroll
        for (int j=0;j<2;j++)
            wmma::store_matrix_sync(&Cs[(wm*32+i*16)*68 + wn*32 + j*16], c[i][j], 68, wmma::mem_row_major);
    __syncthreads();
    #pragma unroll
    for (int t=0;t<8;t++) {
        int idx = tid + t*128;
        int row = idx >> 4, q = idx & 15;
        float4 v = *(float4*)&Cs[row*68 + q*4];
        if (biasz) {
            float4 bv = *(const float4*)(biasz + bn + q*4);
            v.x += bv.x; v.y += bv.y; v.z += bv.z; v.w += bv.w;
        }
        if (resz) {
            float4 rv = *(const float4*)(resz + (size_t)(bm+row)*ldres + bn + q*4);
            v.x += rv.x; v.y += rv.y; v.z += rv.z; v.w += rv.w;
        }
        if (relu) {
            v.x = fmaxf(v.x,0.f); v.y = fmaxf(v.y,0.f);
            v.z = fmaxf(v.z,0.f); v.w = fmaxf(v.w,0.f);
        }
        *(float4*)(Cz + (size_t)(bm+row)*ldc + bn + q*4) = v;
    }
}

// launch helpers (stream-aware)
static void gemmS(cudaStream_t st, const float* A, int lda, long aStep,
                  const float* W, int ldb, long wStep,
                  const float* bias, long bStep,
                  const float* res, int ldres, long rStep, int relu,
                  float* C, int ldc, long cStep,
                  int M, int N, int K, int nz)
{
    dim3 grid(N/64, M/64, nz);
    tf32_gemm_small_b<<<grid,128,3*SMBUF*4,st>>>(M,N,K,A,lda,aStep,W,ldb,wStep,bias,bStep,
                                                 res,ldres,rStep,relu,C,ldc,cStep);
}
static void gemmBnc(cudaStream_t st, const float* A, int lda, long aStep,
                    const float* W, int ldb, long wStep,
                    const float* bias, long bStep,
                    const float* res, int ldres, long rStep, int relu,
                    float* C, int ldc, long cStep,
                    int M, int N, int K, int nz)
{
    dim3 grid(N/128, M/128, nz);
    tf32_gemm_bignc<<<grid,256,3*BIGBUF*4,st>>>(M,N,K,A,lda,aStep,W,ldb,wStep,bias,bStep,
                                                res,ldres,rStep,relu,C,ldc,cStep);
}
static void gemm1(cudaStream_t st, const float* A, int lda, const float* W, int ldb,
                  const float* bias, const float* res, int ldres, int relu,
                  float* C, int ldc, int M, int N, int K)
{
    gemmS(st, A,lda,0, W,ldb,0, bias,0, res,ldres,0,relu, C,ldc,0, M,N,K, 1);
}

// ---------------- LayerNorm ----------------
__global__ void ln_kernel(const float* __restrict__ X,
                          const float* __restrict__ g,
                          const float* __restrict__ b,
                          float* __restrict__ Y)
{
    const int row = blockIdx.x;
    const int tid = threadIdx.x;
    const float* x = X + (size_t)row * D;
    float v0 = x[tid], v1 = x[tid+256];
    __shared__ float red[16];

    float s = v0 + v1;
    #pragma unroll
    for (int o=16;o>0;o>>=1) s += __shfl_xor_sync(0xffffffffu, s, o);
    if ((tid & 31) == 0) red[tid>>5] = s;
    __syncthreads();
    if (tid < 32) {
        float t = (tid < 8) ? red[tid] : 0.f;
        #pragma unroll
        for (int o=4;o>0;o>>=1) t += __shfl_xor_sync(0xffffffffu, t, o);
        if (tid == 0) red[8] = t;
    }
    __syncthreads();
    const float mean = red[8] * (1.f/512.f);
    const float d0 = v0 - mean, d1 = v1 - mean;
    s = d0*d0 + d1*d1;
    #pragma unroll
    for (int o=16;o>0;o>>=1) s += __shfl_xor_sync(0xffffffffu, s, o);
    if ((tid & 31) == 0) red[tid>>5] = s;
    __syncthreads();
    if (tid < 32) {
        float t = (tid < 8) ? red[tid] : 0.f;
        #pragma unroll
        for (int o=4;o>0;o>>=1) t += __shfl_xor_sync(0xffffffffu, t, o);
        if (tid == 0) red[9] = t;
    }
    __syncthreads();
    const float stdv = sqrtf(red[9] * (1.f/512.f));
    const float inv = 1.f / (stdv + 1e-6f);
    Y[(size_t)row*D + tid      ] = g[tid]     * d0 * inv + b[tid];
    Y[(size_t)row*D + tid + 256] = g[tid+256] * d1 * inv + b[tid+256];
}

// ---------------- generic strided attention ----------------
__global__ void attn_kernel(const float* __restrict__ Q,
                            const float* __restrict__ K,
                            const float* __restrict__ V,
                            float* __restrict__ O,
                            const int* __restrict__ mask,
                            int maskMode, int maskDiv,
                            int Lq, int Lk,
                            int qDiv, int kOuter, int kDiv, int kStride,
                            float scale)
{
    extern __shared__ float sm[];
    float* Ks = sm;
    float* Vs = Ks + Lk*65;
    float* qs = Vs + Lk*65;
    float* ps = qs + 4*64;

    const int i = blockIdx.x;
    const int h = blockIdx.y;
    const int tid = threadIdx.x;
    const int lane = tid & 31;
    const int w = tid >> 5;

    const size_t kBase = (size_t)(i/kDiv)*kOuter + (size_t)(i%kDiv);

    for (int idx = tid; idx < Lk*64; idx += 128) {
        int tk = idx >> 6, d = idx & 63;
        size_t grow = (kBase + (size_t)tk*kStride)*D + h*DK + d;
        Ks[tk*65+d] = K[grow];
        Vs[tk*65+d] = V[grow];
    }
    __syncthreads();

    const int qb = (i/qDiv) * Lq;
    const int nj = (Lk + 31) >> 5;

    for (int tq = w; tq < Lq; tq += 4) {
        size_t qoff = (size_t)(qb + tq)*D + h*DK;
        qs[w*64 + lane]      = Q[qoff + lane];
        qs[w*64 + lane + 32] = Q[qoff + lane + 32];
        __syncwarp();

        float sc[4];
        #pragma unroll
        for (int j=0;j<4;j++) sc[j] = -INFINITY;

        for (int j=0;j<nj;j++) {
            int k = lane + (j<<5);
            if (k < Lk) {
                float dot = 0.f;
                const float* kr = Ks + k*65;
                const float* qq = qs + w*64;
                #pragma unroll
                for (int d=0; d<64; d++) dot += qq[d]*kr[d];
                dot *= scale;
                if (maskMode == 1) {
                    if (mask[(size_t)(i/maskDiv)*Lk + k] == 0) dot = -1e9f;
                } else if (maskMode == 2) {
                    if (mask[((size_t)i*Lq + tq)*Lk + k] == 0) dot = -1e9f;
                }
                sc[j] = dot;
            }
        }
        float mx = -INFINITY;
        for (int j=0;j<nj;j++) mx = fmaxf(mx, sc[j]);
        #pragma unroll
        for (int o=16;o>0;o>>=1) mx = fmaxf(mx, __shfl_xor_sync(0xffffffffu, mx, o));

        float e[4]; float sum = 0.f;
        for (int j=0;j<nj;j++) {
            e[j] = (sc[j] == -INFINITY) ? 0.f : __expf(sc[j] - mx);
            sum += e[j];
        }
        #pragma unroll
        for (int o=16;o>0;o>>=1) sum += __shfl_xor_sync(0xffffffffu, sum, o);
        const float inv = 1.f / sum;
        for (int j=0;j<nj;j++) {
            int k = lane + (j<<5);
            if (k < Lk) ps[w*Lk + k] = e[j] * inv;
        }
        __syncwarp();

        float o0 = 0.f, o1 = 0.f;
        for (int k=0;k<Lk;k++) {
            float p = ps[w*Lk + k];
            o0 += p * Vs[k*65 + lane];
            o1 += p * Vs[k*65 + lane + 32];
        }
        size_t orow = ((size_t)i*Lq + tq)*D + h*DK;
        O[orow + lane]      = o0;
        O[orow + lane + 32] = o1;
        __syncwarp();
    }
}

static void launch_attn(cudaStream_t st,
                        const float* Q, const float* K, const float* V, float* O,
                        const int* mask, int maskMode, int maskDiv,
                        int nb, int Lq, int Lk,
                        int qDiv, int kOuter, int kDiv, int kStride)
{
    dim3 grid(nb, NH);
    size_t smem = (size_t)(2*Lk*65 + 4*64 + 4*Lk) * sizeof(float);
    attn_kernel<<<grid, 128, smem, st>>>(Q, K, V, O, mask, maskMode, maskDiv,
                                         Lq, Lk, qDiv, kOuter, kDiv, kStride, 0.125f);
}

// ---------------- fold attention ----------------
__global__ void fold_attn_kernel(const float* __restrict__ O,
                                 const float* __restrict__ Qo,
                                 const float* __restrict__ sb,
                                 const int* __restrict__ mask, int maskApply,
                                 float* __restrict__ ctx, int Lk)
{
    extern __shared__ float sm[];
    float* Os = sm;
    float* sc = Os + Lk*512;
    float* pp = sc + 512;

    const int u = blockIdx.x;
    const int tid = threadIdx.x;
    const int h = tid >> 5;
    const int lane = tid & 31;
    const size_t base = (size_t)(u >> 6) * Lk * 64 + (u & 63);

    for (int idx = tid; idx < Lk*512; idx += 256) {
        int s = idx >> 9, d = idx & 511;
        Os[idx] = O[(base + (size_t)s*64)*D + d];
    }
    __syncthreads();

    float qreg[16];
    #pragma unroll
    for (int i=0;i<16;i++) qreg[i] = Qo[(size_t)u*(NH*D) + h*D + i*32 + lane];

    const float sbase = sb[u*NH + h];

    for (int s = 0; s < Lk; s++) {
        float dot = 0.f;
        const float* row = Os + s*512;
        #pragma unroll
        for (int i=0;i<16;i++) dot += qreg[i] * row[i*32 + lane];
        #pragma unroll
        for (int o=16;o>0;o>>=1) dot += __shfl_xor_sync(0xffffffffu, dot, o);
        float score = (sbase + dot) * 0.125f;
        if (maskApply && mask[(u>>6)*Lk + s] == 0) score = -1e9f;
        if (lane == 0) sc[h*64 + s] = score;
    }
    __syncwarp();

    float v0 = (lane      < Lk) ? sc[h*64 + lane]      : -INFINITY;
    float v1 = (lane + 32 < Lk) ? sc[h*64 + lane + 32] : -INFINITY;
    float mx = fmaxf(v0, v1);
    #pragma unroll
    for (int o=16;o>0;o>>=1) mx = fmaxf(mx, __shfl_xor_sync(0xffffffffu, mx, o));
    float e0 = (lane      < Lk) ? __expf(v0 - mx) : 0.f;
    float e1 = (lane + 32 < Lk) ? __expf(v1 - mx) : 0.f;
    float sum = e0 + e1;
    #pragma unroll
    for (int o=16;o>0;o>>=1) sum += __shfl_xor_sync(0xffffffffu, sum, o);
    const float inv = 1.f / sum;
    if (lane      < Lk) pp[h*64 + lane]      = e0 * inv;
    if (lane + 32 < Lk) pp[h*64 + lane + 32] = e1 * inv;
    __syncwarp();

    #pragma unroll
    for (int i=0;i<16;i++) {
        float acc = 0.f;
        for (int s=0;s<Lk;s++)
            acc += pp[h*64 + s] * Os[s*512 + i*32 + lane];
        ctx[(size_t)u*(NH*D) + h*D + i*32 + lane] = acc;
    }
}

// ---------------- small helpers ----------------
__global__ void transpose512(const float* __restrict__ in, float* __restrict__ out)
{
    __shared__ float t[32][33];
    int bx = blockIdx.x*32, by = blockIdx.y*32;
    for (int j = threadIdx.y; j < 32; j += 8)
        t[j][threadIdx.x] = in[(size_t)(by+j)*D + bx + threadIdx.x];
    __syncthreads();
    for (int j = threadIdx.y; j < 32; j += 8)
        out[(size_t)(bx+j)*D + by + threadIdx.x] = t[threadIdx.x][j];
}

__global__ void addrow_kernel(const float* __restrict__ a, const float* __restrict__ bvec,
                              float* __restrict__ c)
{
    int u = blockIdx.x, d = threadIdx.x;
    c[(size_t)u*D + d] = a[(size_t)u*D + d] + bvec[d];
}

__global__ void sbase_kernel(const float* __restrict__ Qp, const float* __restrict__ mmk,
                             float* __restrict__ sb)
{
    int u = blockIdx.x;
    int h = threadIdx.x >> 5, lane = threadIdx.x & 31;
    const float* q = Qp  + (size_t)u*D + h*64;
    const float* m = mmk + (size_t)u*D + h*64;
    float s = q[lane]*m[lane] + q[lane+32]*m[lane+32];
    #pragma unroll
    for (int o=16;o>0;o>>=1) s += __shfl_xor_sync(0xffffffffu, s, o);
    if (lane == 0) sb[u*NH + h] = s;
}

__global__ void add_kernel(const float* __restrict__ a, const float* __restrict__ b,
                           float* __restrict__ c, int n)
{
    int i = blockIdx.x*256 + threadIdx.x;
    if (i < n) c[i] = a[i] + b[i];
}

// ---------------- persistent stream/event resources ----------------
static cudaStream_t g_s2 = nullptr, g_s3 = nullptr;
static cudaEvent_t  g_evStart = nullptr, g_evEnc = nullptr, g_evA = nullptr,
                    g_evRound = nullptr, g_evFork = nullptr, g_evJoin = nullptr;

// ---------------- driver ----------------
extern "C" void kernel_launch(void* const* d_in, const int* in_sizes, int n_in,
                              void* d_out, int out_size)
{
    const float* x        = (const float*)d_in[0];
    const float* vft      = (const float*)d_in[1];
    const float* enc_his  = (const float*)d_in[2];
    const float* enc_cap  = (const float*)d_in[3];
    const float* enc_qry  = (const float*)d_in[4];
    const int*   trg_mask = (const int*)  d_in[5];
    const int*   his_mask = (const int*)  d_in[6];
    const int*   cap_mask = (const int*)  d_in[7];
    const int*   qry_mask = (const int*)  d_in[8];
    const int*   tmp_mask = (const int*)  d_in[9];
    const float* attn_w   = (const float*)d_in[10];
    const float* attn_b   = (const float*)d_in[11];
    const float* ff_w1    = (const float*)d_in[12];
    const float* ff_b1    = (const float*)d_in[13];
    const float* ff_w2    = (const float*)d_in[14];
    const float* ff_b2    = (const float*)d_in[15];
    const float* ln_g     = (const float*)d_in[16];
    const float* ln_b     = (const float*)d_in[17];
    float* outp = (float*)d_out;

    if (!g_s2) {
        cudaStreamCreateWithFlags(&g_s2, cudaStreamNonBlocking);
        cudaStreamCreateWithFlags(&g_s3, cudaStreamNonBlocking);
        cudaEventCreateWithFlags(&g_evStart, cudaEventDisableTiming);
        cudaEventCreateWithFlags(&g_evEnc,  cudaEventDisableTiming);
        cudaEventCreateWithFlags(&g_evA,    cudaEventDisableTiming);
        cudaEventCreateWithFlags(&g_evRound,cudaEventDisableTiming);
        cudaEventCreateWithFlags(&g_evFork, cudaEventDisableTiming);
        cudaEventCreateWithFlags(&g_evJoin, cudaEventDisableTiming);
    }
    cudaStream_t s0 = 0, s2 = g_s2, s3 = g_s3;

    float *bigKV,*big2,*qkv,*kvEnc,*lnb,*ob,*cur,*ts,*mid,*mmb,*mmkv,*sb,*qo,*ctx,*w12,*w1t;
    float *bigKV2,*big3,*lnB,*qB,*oB,*st,*midB,*mmbB,*mmkvB,*sbB,*qoB,*ctxB,*w12B,*w1tB;
    float *vftR,*wR;
    cudaGetSymbolAddress((void**)&bigKV, g_bigKV);
    cudaGetSymbolAddress((void**)&big2,  g_big2);
    cudaGetSymbolAddress((void**)&qkv,   g_qkv);
    cudaGetSymbolAddress((void**)&kvEnc, g_kvEnc);
    cudaGetSymbolAddress((void**)&lnb,   g_ln);
    cudaGetSymbolAddress((void**)&ob,    g_o);
    cudaGetSymbolAddress((void**)&cur,   g_cur);
    cudaGetSymbolAddress((void**)&ts,    g_ts);
    cudaGetSymbolAddress((void**)&mid,   g_mid);
    cudaGetSymbolAddress((void**)&mmb,   g_mmb);
    cudaGetSymbolAddress((void**)&mmkv,  g_mmkv);
    cudaGetSymbolAddress((void**)&sb,    g_sb);
    cudaGetSymbolAddress((void**)&qo,    g_qo);
    cudaGetSymbolAddress((void**)&ctx,   g_ctx);
    cudaGetSymbolAddress((void**)&w12,   g_w12);
    cudaGetSymbolAddress((void**)&w1t,   g_w1t);
    cudaGetSymbolAddress((void**)&bigKV2,g_bigKV2);
    cudaGetSymbolAddress((void**)&big3,  g_big3);
    cudaGetSymbolAddress((void**)&lnB,   g_lnB);
    cudaGetSymbolAddress((void**)&qB,    g_qB);
    cudaGetSymbolAddress((void**)&oB,    g_oB);
    cudaGetSymbolAddress((void**)&st,    g_st);
    cudaGetSymbolAddress((void**)&midB,  g_midB);
    cudaGetSymbolAddress((void**)&mmbB,  g_mmbB);
    cudaGetSymbolAddress((void**)&mmkvB, g_mmkvB);
    cudaGetSymbolAddress((void**)&sbB,   g_sbB);
    cudaGetSymbolAddress((void**)&qoB,   g_qoB);
    cudaGetSymbolAddress((void**)&ctxB,  g_ctxB);
    cudaGetSymbolAddress((void**)&w12B,  g_w12B);
    cudaGetSymbolAddress((void**)&w1tB,  g_w1tB);
    cudaGetSymbolAddress((void**)&vftR,  g_vftR);
    cudaGetSymbolAddress((void**)&wR,    g_wR);

    float* qb = qkv;
    float* kb = qkv + (size_t)2048*D;
    float* vb = qkv + (size_t)4096*D;
    float* kHis = kvEnc;
    float* kCap = kvEnc + (size_t)4096*D;
    float* kQry = kvEnc + (size_t)6144*D;
    float* big0 = bigKV;
    float* big1 = bigKV + (size_t)NV*D;
    float* big0B = bigKV2;
    float* big1B = bigKV2 + (size_t)NV*D;
    float* mmk = mmkv;
    float* mmv = mmkv + (size_t)NT*D;
    float* mmkB = mmkvB;
    float* mmvB = mmkvB + (size_t)NT*D;
    float* w1 = w12;
    float* w2 = w12 + (size_t)D*D;
    float* w1B = w12B;
    float* w2B = w12B + (size_t)D*D;
    float* wR45 = wR;
    float* wR67 = wR + (size_t)2*D*D;

    cudaFuncSetAttribute(attn_kernel, cudaFuncAttributeMaxDynamicSharedMemorySize, 73728);
    cudaFuncSetAttribute(fold_attn_kernel, cudaFuncAttributeMaxDynamicSharedMemorySize, 64*512*4 + 4096);
    cudaFuncSetAttribute(tf32_gemm_big_b, cudaFuncAttributeMaxDynamicSharedMemorySize, 3*BIGBUF*4);
    cudaFuncSetAttribute(tf32_gemm_bignc, cudaFuncAttributeMaxDynamicSharedMemorySize, 3*BIGBUF*4);
    cudaFuncSetAttribute(tf32_gemm_small_b, cudaFuncAttributeMaxDynamicSharedMemorySize, 3*SMBUF*4);

    #define WATT(l,j) (attn_w + ((size_t)(l)*4+(j))*D*D)
    #define BATT(l,j) (attn_b + ((size_t)(l)*4+(j))*D)
    const long ZW = (long)D*D;
    const long ZB = D;
    const long ZKV = (long)2048*D;

    // ======== PRELUDE ========
    cudaEventRecord(g_evStart, s0);
    cudaStreamWaitEvent(s2, g_evStart, 0);
    cudaStreamWaitEvent(s3, g_evStart, 0);

    // s3: round vft + both weight pairs -> evRound, then K6/V6 (convert-free)
    {
        long n4 = (long)NV*D/4;
        round_tf32_kernel<<<(unsigned)((n4+255)/256),256,0,s3>>>(vft, vftR, n4);
        long w4 = (long)2*D*D/4;
        round_tf32_kernel<<<(unsigned)((w4+255)/256),256,0,s3>>>(WATT(4,1), wR45, w4);
        round_tf32_kernel<<<(unsigned)((w4+255)/256),256,0,s3>>>(WATT(6,1), wR67, w4);
        cudaEventRecord(g_evRound, s3);
    }
    gemmBnc(s3, vftR,D,0, wR67,D,ZW, BATT(6,1),ZB, nullptr,0,0,0, big0B,D,(long)NV*D, NV,D,D, 2); // K6,V6
    gemmS(s3, WATT(6,3),D,0, WATT(7,1),D,ZW, nullptr,0, nullptr,0,0,0, w1B,D,(long)D*D, D,D,D, 2);
    transpose512<<<dim3(16,16),dim3(32,8),0,s3>>>(w1B, w1tB);

    // s2: encoder K/V -> evEnc; then K4/V4 + fold-5 weight products -> evA
    gemmS(s2, enc_his,D,0, WATT(1,1),D,ZW, BATT(1,1),ZB, nullptr,0,0,0, kHis,D,(long)2048*D, 2048,D,D, 2);
    gemmS(s2, enc_cap,D,0, WATT(2,1),D,ZW, BATT(2,1),ZB, nullptr,0,0,0, kCap,D,(long)1024*D, 1024,D,D, 2);
    gemmS(s2, enc_qry,D,0, WATT(3,1),D,ZW, BATT(3,1),ZB, nullptr,0,0,0, kQry,D,(long)512*D,  512,D,D, 2);
    cudaEventRecord(g_evEnc, s2);
    cudaStreamWaitEvent(s2, g_evRound, 0);
    gemmBnc(s2, vftR,D,0, wR45,D,ZW, BATT(4,1),ZB, nullptr,0,0,0, big0,D,(long)NV*D, NV,D,D, 2);  // K4,V4
    gemmS(s2, WATT(4,3),D,0, WATT(5,1),D,ZW, nullptr,0, nullptr,0,0,0, w1,D,(long)D*D, D,D,D, 2);
    transpose512<<<dim3(16,16),dim3(32,8),0,s2>>>(w1, w1t);
    cudaEventRecord(g_evA, s2);

    // ===== MHA0 (s0) =====
    ln_kernel<<<NT,256,0,s0>>>(x, ln_g + 0*D, ln_b + 0*D, lnb);
    gemmS(s0, lnb,D,0, WATT(0,0),D,ZW, BATT(0,0),ZB, nullptr,0,0,0, qb,D,ZKV, NT,D,D, 3);
    launch_attn(s0, qb, kb, vb, ob, trg_mask, 2, 1, BSZ, TTRG, TTRG, 1, TTRG, 1, 1);
    gemm1(s0, ob,D, WATT(0,3),D, BATT(0,3), x,D,0, cur,D, NT, D, D);

    cudaStreamWaitEvent(s0, g_evEnc, 0);

    // ===== MHA1 =====
    ln_kernel<<<NT,256,0,s0>>>(cur, ln_g + 1*D, ln_b + 1*D, lnb);
    gemm1(s0, lnb,D, WATT(1,0),D, BATT(1,0), nullptr,0,0, qb,D, NT, D, D);
    launch_attn(s0, qb, kHis, kHis + (size_t)2048*D, ob, his_mask, 1, 1, BSZ, TTRG, 128, 1, 128, 1, 1);
    gemm1(s0, ob,D, WATT(1,3),D, BATT(1,3), cur,D,0, cur,D, NT, D, D);

    // ===== MHA2 =====
    ln_kernel<<<NT,256,0,s0>>>(cur, ln_g + 2*D, ln_b + 2*D, lnb);
    gemm1(s0, lnb,D, WATT(2,0),D, BATT(2,0), nullptr,0,0, qb,D, NT, D, D);
    launch_attn(s0, qb, kCap, kCap + (size_t)1024*D, ob, cap_mask, 1, 1, BSZ, TTRG, 64, 1, 64, 1, 1);
    gemm1(s0, ob,D, WATT(2,3),D, BATT(2,3), cur,D,0, cur,D, NT, D, D);

    // ===== MHA3 -> mm (cur) =====
    ln_kernel<<<NT,256,0,s0>>>(cur, ln_g + 3*D, ln_b + 3*D, lnb);
    gemm1(s0, lnb,D, WATT(3,0),D, BATT(3,0), nullptr,0,0, qb,D, NT, D, D);
    launch_attn(s0, qb, kQry, kQry + (size_t)512*D, ob, qry_mask, 1, 1, BSZ, TTRG, 32, 1, 32, 1, 1);
    gemm1(s0, ob,D, WATT(3,3),D, BATT(3,3), cur,D,0, cur,D, NT, D, D);
    // cur == mm

    // ======== FORK: branch B on s3 ========
    cudaEventRecord(g_evFork, s0);
    cudaStreamWaitEvent(s3, g_evFork, 0);

    // ---- Branch B: MHA6 ----
    ln_kernel<<<NT,256,0,s3>>>(cur, ln_g + 7*D, ln_b + 7*D, lnB);
    gemm1(s3, lnB,D, WATT(6,0),D, BATT(6,0), nullptr,0,0, qB,D, NT, D, D);
    launch_attn(s3, qB, big0B, big1B, big3, nullptr, 0, 1,
                BSZ*TT, TTRG, SSP, TT, SSP, 1, 1);                               // O6
    // ---- Branch B: MHA7 folded ----
    {
        const float* bo = BATT(6,3);
        addrow_kernel<<<NT,512,0,s3>>>(cur, bo, mmbB);
        gemmS(s3, mmbB,D,0, WATT(7,1),D,ZW, BATT(7,1),ZB, nullptr,0,0,0, mmkB,D,(long)NT*D, NT,D,D, 2);
        ln_kernel<<<NT,256,0,s3>>>(cur, ln_g + 8*D, ln_b + 8*D, lnB);
        gemm1(s3, lnB,D, WATT(7,0),D, BATT(7,0), nullptr,0,0, qB,D, NT, D, D);
        gemmS(s3, qB,D,64, w1tB,D,(long)64*D, nullptr,0, nullptr,0,0,0, qoB,NH*D,(long)D, NT,D,64, 8);
        sbase_kernel<<<NT,256,0,s3>>>(qB, mmkB, sbB);
        fold_attn_kernel<<<NT,256, TT*512*4 + 4096, s3>>>(big3, qoB, sbB, tmp_mask, 1, ctxB, TT);
        gemmS(s3, ctxB,NH*D,(long)D, w2B,D,64, nullptr,0, mmvB,D,64,0, oB,D,64, NT,64,D, 8);
        gemm1(s3, oB,D, WATT(7,3),D, BATT(7,3), cur,D,0, st,D, NT, D, D);
    }
    // ---- Branch B: FFN1 ----
    ln_kernel<<<NT,256,0,s3>>>(st, ln_g + 9*D, ln_b + 9*D, lnB);
    gemm1(s3, lnB,D, ff_w1 + 1*(size_t)D*DFF,DFF, ff_b1 + 1*DFF, nullptr,0,1, midB,DFF, NT, DFF, D);
    gemm1(s3, midB,DFF, ff_w2 + 1*(size_t)DFF*D,D, ff_b2 + 1*D, st,D,0, st,D, NT, D, DFF);
    cudaEventRecord(g_evJoin, s3);

    // ======== Branch A on s0 ========
    cudaStreamWaitEvent(s0, g_evA, 0);
    ln_kernel<<<NT,256,0,s0>>>(cur, ln_g + 4*D, ln_b + 4*D, lnb);
    gemm1(s0, lnb,D, WATT(4,0),D, BATT(4,0), nullptr,0,0, qb,D, NT, D, D);
    launch_attn(s0, qb, big0, big1, big2, tmp_mask, 1, SSP,
                BSZ*SSP, TTRG, TT, SSP, TT*SSP, SSP, SSP);                       // O4
    // ---- MHA5 folded ----
    {
        const float* bo = BATT(4,3);
        addrow_kernel<<<NT,512,0,s0>>>(cur, bo, mmb);
        gemmS(s0, mmb,D,0, WATT(5,1),D,ZW, BATT(5,1),ZB, nullptr,0,0,0, mmk,D,(long)NT*D, NT,D,D, 2);
        ln_kernel<<<NT,256,0,s0>>>(cur, ln_g + 5*D, ln_b + 5*D, lnb);
        gemm1(s0, lnb,D, WATT(5,0),D, BATT(5,0), nullptr,0,0, qb,D, NT, D, D);
        gemmS(s0, qb,D,64, w1t,D,(long)64*D, nullptr,0, nullptr,0,0,0, qo,NH*D,(long)D, NT,D,64, 8);
        sbase_kernel<<<NT,256,0,s0>>>(qb, mmk, sb);
        fold_attn_kernel<<<NT,256, SSP*512*4 + 4096, s0>>>(big2, qo, sb, nullptr, 0, ctx, SSP);
        gemmS(s0, ctx,NH*D,(long)D, w2,D,64, nullptr,0, mmv,D,64,0, ob,D,64, NT,64,D, 8);
        gemm1(s0, ob,D, WATT(5,3),D, BATT(5,3), cur,D,0, ts,D, NT, D, D);
    }
    // ---- FFN0 ----
    ln_kernel<<<NT,256,0,s0>>>(ts, ln_g + 6*D, ln_b + 6*D, lnb);
    gemm1(s0, lnb,D, ff_w1 + 0*(size_t)D*DFF,DFF, ff_b1 + 0*DFF, nullptr,0,1, mid,DFF, NT, DFF, D);
    gemm1(s0, mid,DFF, ff_w2 + 0*(size_t)DFF*D,D, ff_b2 + 0*D, ts,D,0, ts,D, NT, D, DFF);

    // ======== JOIN ========
    cudaStreamWaitEvent(s0, g_evJoin, 0);

    // ===== out = ts + st; FFN2 =====
    add_kernel<<<(NT*D+255)/256,256,0,s0>>>(ts, st, qb, NT*D);
    ln_kernel<<<NT,256,0,s0>>>(qb, ln_g + 10*D, ln_b + 10*D, lnb);
    gemm1(s0, lnb,D, ff_w1 + 2*(size_t)D*DFF,DFF, ff_b1 + 2*DFF, nullptr,0,1, mid,DFF, NT, DFF, D);
    gemm1(s0, mid,DFF, ff_w2 + 2*(size_t)DFF*D,D, ff_b2 + 2*D, qb,D,0, outp,D, NT, D, DFF);
}

// round 17
// speedup vs baseline: 1.3162x; 1.3162x over previous
#include <cuda_runtime.h>
#include <cuda_bf16.h>
#include <math.h>
#include <stdint.h>
#include <mma.h>
using namespace nvcuda;

// ---------------- constants ----------------
#define D     512
#define NH    8
#define DK    64
#define BSZ   16
#define TTRG  64
#define TT    64
#define SSP   49
#define DFF   2048
#define NT    1024
#define NV    50176
#define NBIG  65536

// ---------------- scratch (branch A + shared) ----------------
__device__ float g_bigKV[(size_t)2 * NV * D];   // K4,V4
__device__ float g_big2[(size_t)NV * D];        // O4
__device__ float g_qkv[(size_t)6144 * D];
__device__ float g_kvEnc[(size_t)7168 * D];
__device__ float g_ln [(size_t)NT * D];
__device__ float g_o  [(size_t)NT * D];
__device__ float g_cur[(size_t)NT * D];
__device__ float g_ts [(size_t)NT * D];
__device__ float g_mid[(size_t)NT * DFF];
__device__ float g_mmb[(size_t)NT * D];
__device__ float g_mmkv[(size_t)2 * NT * D];
__device__ float g_sb [(size_t)NT * NH];
__device__ float g_qo [(size_t)NT * NH * D];
__device__ float g_ctx[(size_t)NT * NH * D];
__device__ float g_w12[(size_t)2 * D * D];
__device__ float g_w1t[(size_t)D * D];
// ---------------- scratch (branch B private) ----------------
__device__ float g_bigKV2[(size_t)2 * NV * D];  // K6,V6
__device__ float g_big3[(size_t)NBIG * D];      // O6
__device__ float g_lnB [(size_t)NT * D];
__device__ float g_qB  [(size_t)NT * D];
__device__ float g_oB  [(size_t)NT * D];
__device__ float g_st  [(size_t)NT * D];
__device__ float g_midB[(size_t)NT * DFF];
__device__ float g_mmbB[(size_t)NT * D];
__device__ float g_mmkvB[(size_t)2 * NT * D];
__device__ float g_sbB [(size_t)NT * NH];
__device__ float g_qoB [(size_t)NT * NH * D];
__device__ float g_ctxB[(size_t)NT * NH * D];
__device__ float g_w12B[(size_t)2 * D * D];
__device__ float g_w1tB[(size_t)D * D];
// ---------------- bf16 pre-rounded inputs for the big projections ----------
__device__ __align__(16) __nv_bfloat16 g_vftH[(size_t)NV * D];   // 51 MB
__device__ __align__(16) __nv_bfloat16 g_wH  [(size_t)4 * D * D];

// ---------------- cp.async helpers ----------------
__device__ __forceinline__ void cp_async16(void* smem_dst, const void* gsrc) {
    uint32_t s = (uint32_t)__cvta_generic_to_shared(smem_dst);
    asm volatile("cp.async.cg.shared.global [%0], [%1], 16;\n" :: "r"(s), "l"(gsrc));
}
#define CP_COMMIT() asm volatile("cp.async.commit_group;\n" ::: "memory")
#define CP_WAIT(n)  asm volatile("cp.async.wait_group %0;\n" :: "n"(n) : "memory")

// ---------------- fp32 -> bf16 rounding kernel ----------------
__global__ void round_bf16_kernel(const float* __restrict__ in,
                                  __nv_bfloat16* __restrict__ out, long n4)
{
    long i = (long)blockIdx.x*256 + threadIdx.x;
    if (i < n4) {
        float4 v = ((const float4*)in)[i];
        __nv_bfloat162 p0 = __floats2bfloat162_rn(v.x, v.y);
        __nv_bfloat162 p1 = __floats2bfloat162_rn(v.z, v.w);
        ((__nv_bfloat162*)out)[2*i]   = p0;
        ((__nv_bfloat162*)out)[2*i+1] = p1;
    }
}

// ============ bf16 GEMM, batched, 128x128x32, double-buffered (R14 structure) ============
// per-stage smem (bf16 elems): A[128][40] + B[32][136] = 9472
#define HBUF 9472
__global__ void __launch_bounds__(256, 2)
bf16_gemm_big_b(int M, int N, int K,
                const __nv_bfloat16* __restrict__ A, int lda, long aStep,
                const __nv_bfloat16* __restrict__ W, int ldb, long wStep,
                const float* __restrict__ bias, long bStep,
                const float* res, int ldres, long rStep, int relu,
                float* __restrict__ C, int ldc, long cStep)
{
    extern __shared__ char smc[];
    __nv_bfloat16* smh = (__nv_bfloat16*)smc;
    const long z = blockIdx.z;
    A += z*aStep; W += z*wStep;
    const float* biasz = bias ? bias + z*bStep : nullptr;
    const float* resz  = res  ? res  + z*rStep : nullptr;
    float* Cz = C + z*cStep;

    const int tid = threadIdx.x;
    const int wid = tid >> 5;
    const int wm = wid >> 1;     // 0..3
    const int wn = wid & 1;      // 0..1
    const int bm = blockIdx.y * 128;
    const int bn = blockIdx.x * 128;

    wmma::fragment<wmma::accumulator, 16,16,16, float> c[2][4];
    #pragma unroll
    for (int i=0;i<2;i++)
        #pragma unroll
        for (int j=0;j<4;j++) wmma::fill_fragment(c[i][j], 0.f);

    const int nK = K >> 5;       // 32-wide k-tiles

    auto issue = [&](int buf, int k0) {
        __nv_bfloat16* As = smh + buf*HBUF;
        __nv_bfloat16* Bs = As + 128*40;
        #pragma unroll
        for (int t=0;t<2;t++) {                      // A: 128x32 bf16 = 512 x 16B
            int idx = tid + t*256;
            int row = idx >> 2, q = idx & 3;
            cp_async16(&As[row*40 + q*8], A + (size_t)(bm+row)*lda + k0 + q*8);
        }
        #pragma unroll
        for (int t=0;t<2;t++) {                      // B: 32x128 bf16 = 512 x 16B
            int idx = tid + t*256;
            int row = idx >> 4, q = idx & 15;
            cp_async16(&Bs[row*136 + q*8], W + (size_t)(k0+row)*ldb + bn + q*8);
        }
        CP_COMMIT();
    };

    issue(0, 0);
    for (int kt = 0; kt < nK; kt++) {
        if (kt+1 < nK) { issue((kt+1)&1, (kt+1)<<5); CP_WAIT(1); }
        else           { CP_WAIT(0); }
        __syncthreads();
        __nv_bfloat16* As = smh + (kt&1)*HBUF;
        __nv_bfloat16* Bs = As + 128*40;
        #pragma unroll
        for (int ks=0; ks<2; ks++) {                 // two K=16 steps per 32-tile
            wmma::fragment<wmma::matrix_a, 16,16,16, __nv_bfloat16, wmma::row_major> a[2];
            wmma::fragment<wmma::matrix_b, 16,16,16, __nv_bfloat16, wmma::row_major> b[4];
            #pragma unroll
            for (int i=0;i<2;i++)
                wmma::load_matrix_sync(a[i], &As[(wm*32 + i*16)*40 + ks*16], 40);
            #pragma unroll
            for (int j=0;j<4;j++)
                wmma::load_matrix_sync(b[j], &Bs[(ks*16)*136 + wn*64 + j*16], 136);
            #pragma unroll
            for (int i=0;i<2;i++)
                #pragma unroll
                for (int j=0;j<4;j++)
                    wmma::mma_sync(c[i][j], a[i], b[j], c[i][j]);
        }
        __syncthreads();
    }

    float* Cs = (float*)smc;     // [128][132] floats for epilogue
    #pragma unroll
    for (int i=0;i<2;i++)
        #pragma unroll
        for (int j=0;j<4;j++)
            wmma::store_matrix_sync(&Cs[(wm*32+i*16)*132 + wn*64 + j*16], c[i][j], 132, wmma::mem_row_major);
    __syncthreads();
    #pragma unroll
    for (int t=0;t<16;t++) {
        int idx = tid + t*256;
        int row = idx >> 5, q = idx & 31;
        float4 v = *(float4*)&Cs[row*132 + q*4];
        if (biasz) {
            float4 bv = *(const float4*)(biasz + bn + q*4);
            v.x += bv.x; v.y += bv.y; v.z += bv.z; v.w += bv.w;
        }
        if (resz) {
            float4 rv = *(const float4*)(resz + (size_t)(bm+row)*ldres + bn + q*4);
            v.x += rv.x; v.y += rv.y; v.z += rv.z; v.w += rv.w;
        }
        if (relu) {
            v.x = fmaxf(v.x,0.f); v.y = fmaxf(v.y,0.f);
            v.z = fmaxf(v.z,0.f); v.w = fmaxf(v.w,0.f);
        }
        *(float4*)(Cz + (size_t)(bm+row)*ldc + bn + q*4) = v;
    }
}
// dynamic smem = max(2 stages * HBUF * 2B = 37.9KB, epilogue 128*132*4 = 67.6KB)
#define HSMEM (128*132*4)

// ======= tf32 GEMM, batched, 64x64x32, 4 warps, double-buffered (R14) =======
#define SMBUF 4480
__global__ void tf32_gemm_small_b(int M, int N, int K,
                                  const float* __restrict__ A, int lda, long aStep,
                                  const float* __restrict__ W, int ldb, long wStep,
                                  const float* __restrict__ bias, long bStep,
                                  const float* res, int ldres, long rStep, int relu,
                                  float* __restrict__ C, int ldc, long cStep)
{
    __shared__ float sm[2*SMBUF];
    const long z = blockIdx.z;
    A += z*aStep; W += z*wStep;
    const float* biasz = bias ? bias + z*bStep : nullptr;
    const float* resz  = res  ? res  + z*rStep : nullptr;
    float* Cz = C + z*cStep;

    const int tid = threadIdx.x;
    const int wid = tid >> 5;
    const int wm = wid >> 1;
    const int wn = wid & 1;
    const int bm = blockIdx.y * 64;
    const int bn = blockIdx.x * 64;

    wmma::fragment<wmma::accumulator, 16,16,8, float> c[2][2];
    #pragma unroll
    for (int i=0;i<2;i++)
        #pragma unroll
        for (int j=0;j<2;j++) wmma::fill_fragment(c[i][j], 0.f);

    const int nK = K >> 5;

    auto issue = [&](int buf, int k0) {
        float* As = sm + buf*SMBUF;
        float* Bs = As + 64*36;
        #pragma unroll
        for (int t=0;t<4;t++) {
            int idx = tid + t*128;
            int row = idx >> 3, q = idx & 7;
            cp_async16(&As[row*36 + q*4], A + (size_t)(bm+row)*lda + k0 + q*4);
        }
        #pragma unroll
        for (int t=0;t<4;t++) {
            int idx = tid + t*128;
            int row = idx >> 4, q = idx & 15;
            cp_async16(&Bs[row*68 + q*4], W + (size_t)(k0+row)*ldb + bn + q*4);
        }
        CP_COMMIT();
    };

    issue(0, 0);
    for (int kt = 0; kt < nK; kt++) {
        if (kt+1 < nK) { issue((kt+1)&1, (kt+1)<<5); CP_WAIT(1); }
        else           { CP_WAIT(0); }
        __syncthreads();
        float* As = sm + (kt&1)*SMBUF;
        float* Bs = As + 64*36;
        #pragma unroll
        for (int ks=0; ks<4; ks++) {
            wmma::fragment<wmma::matrix_a, 16,16,8, wmma::precision::tf32, wmma::row_major> a[2];
            wmma::fragment<wmma::matrix_b, 16,16,8, wmma::precision::tf32, wmma::row_major> b[2];
            #pragma unroll
            for (int i=0;i<2;i++) {
                wmma::load_matrix_sync(a[i], &As[(wm*32 + i*16)*36 + ks*8], 36);
                #pragma unroll
                for (int e=0;e<a[i].num_elements;e++) a[i].x[e] = wmma::__float_to_tf32(a[i].x[e]);
            }
            #pragma unroll
            for (int j=0;j<2;j++) {
                wmma::load_matrix_sync(b[j], &Bs[(ks*8)*68 + wn*32 + j*16], 68);
                #pragma unroll
                for (int e=0;e<b[j].num_elements;e++) b[j].x[e] = wmma::__float_to_tf32(b[j].x[e]);
            }
            #pragma unroll
            for (int i=0;i<2;i++)
                #pragma unroll
                for (int j=0;j<2;j++)
                    wmma::mma_sync(c[i][j], a[i], b[j], c[i][j]);
        }
        __syncthreads();
    }

    float* Cs = sm;
    #pragma unroll
    for (int i=0;i<2;i++)
        #pragma unroll
        for (int j=0;j<2;j++)
            wmma::store_matrix_sync(&Cs[(wm*32+i*16)*68 + wn*32 + j*16], c[i][j], 68, wmma::mem_row_major);
    __syncthreads();
    #pragma unroll
    for (int t=0;t<8;t++) {
        int idx = tid + t*128;
        int row = idx >> 4, q = idx & 15;
        float4 v = *(float4*)&Cs[row*68 + q*4];
        if (biasz) {
            float4 bv = *(const float4*)(biasz + bn + q*4);
            v.x += bv.x; v.y += bv.y; v.z += bv.z; v.w += bv.w;
        }
        if (resz) {
            float4 rv = *(const float4*)(resz + (size_t)(bm+row)*ldres + bn + q*4);
            v.x += rv.x; v.y += rv.y; v.z += rv.z; v.w += rv.w;
        }
        if (relu) {
            v.x = fmaxf(v.x,0.f); v.y = fmaxf(v.y,0.f);
            v.z = fmaxf(v.z,0.f); v.w = fmaxf(v.w,0.f);
        }
        *(float4*)(Cz + (size_t)(bm+row)*ldc + bn + q*4) = v;
    }
}

// launch helpers
static void gemmS(cudaStream_t st, const float* A, int lda, long aStep,
                  const float* W, int ldb, long wStep,
                  const float* bias, long bStep,
                  const float* res, int ldres, long rStep, int relu,
                  float* C, int ldc, long cStep,
                  int M, int N, int K, int nz)
{
    dim3 grid(N/64, M/64, nz);
    tf32_gemm_small_b<<<grid,128,0,st>>>(M,N,K,A,lda,aStep,W,ldb,wStep,bias,bStep,
                                         res,ldres,rStep,relu,C,ldc,cStep);
}
static void gemmH(cudaStream_t st, const __nv_bfloat16* A, int lda, long aStep,
                  const __nv_bfloat16* W, int ldb, long wStep,
                  const float* bias, long bStep,
                  const float* res, int ldres, long rStep, int relu,
                  float* C, int ldc, long cStep,
                  int M, int N, int K, int nz)
{
    dim3 grid(N/128, M/128, nz);
    bf16_gemm_big_b<<<grid,256,HSMEM,st>>>(M,N,K,A,lda,aStep,W,ldb,wStep,bias,bStep,
                                           res,ldres,rStep,relu,C,ldc,cStep);
}
static void gemm1(cudaStream_t st, const float* A, int lda, const float* W, int ldb,
                  const float* bias, const float* res, int ldres, int relu,
                  float* C, int ldc, int M, int N, int K)
{
    gemmS(st, A,lda,0, W,ldb,0, bias,0, res,ldres,0,relu, C,ldc,0, M,N,K, 1);
}

// ---------------- LayerNorm ----------------
__global__ void ln_kernel(const float* __restrict__ X,
                          const float* __restrict__ g,
                          const float* __restrict__ b,
                          float* __restrict__ Y)
{
    const int row = blockIdx.x;
    const int tid = threadIdx.x;
    const float* x = X + (size_t)row * D;
    float v0 = x[tid], v1 = x[tid+256];
    __shared__ float red[16];

    float s = v0 + v1;
    #pragma unroll
    for (int o=16;o>0;o>>=1) s += __shfl_xor_sync(0xffffffffu, s, o);
    if ((tid & 31) == 0) red[tid>>5] = s;
    __syncthreads();
    if (tid < 32) {
        float t = (tid < 8) ? red[tid] : 0.f;
        #pragma unroll
        for (int o=4;o>0;o>>=1) t += __shfl_xor_sync(0xffffffffu, t, o);
        if (tid == 0) red[8] = t;
    }
    __syncthreads();
    const float mean = red[8] * (1.f/512.f);
    const float d0 = v0 - mean, d1 = v1 - mean;
    s = d0*d0 + d1*d1;
    #pragma unroll
    for (int o=16;o>0;o>>=1) s += __shfl_xor_sync(0xffffffffu, s, o);
    if ((tid & 31) == 0) red[tid>>5] = s;
    __syncthreads();
    if (tid < 32) {
        float t = (tid < 8) ? red[tid] : 0.f;
        #pragma unroll
        for (int o=4;o>0;o>>=1) t += __shfl_xor_sync(0xffffffffu, t, o);
        if (tid == 0) red[9] = t;
    }
    __syncthreads();
    const float stdv = sqrtf(red[9] * (1.f/512.f));
    const float inv = 1.f / (stdv + 1e-6f);
    Y[(size_t)row*D + tid      ] = g[tid]     * d0 * inv + b[tid];
    Y[(size_t)row*D + tid + 256] = g[tid+256] * d1 * inv + b[tid+256];
}

// ---------------- generic strided attention ----------------
__global__ void attn_kernel(const float* __restrict__ Q,
                            const float* __restrict__ K,
                            const float* __restrict__ V,
                            float* __restrict__ O,
                            const int* __restrict__ mask,
                            int maskMode, int maskDiv,
                            int Lq, int Lk,
                            int qDiv, int kOuter, int kDiv, int kStride,
                            float scale)
{
    extern __shared__ float sm[];
    float* Ks = sm;
    float* Vs = Ks + Lk*65;
    float* qs = Vs + Lk*65;
    float* ps = qs + 4*64;

    const int i = blockIdx.x;
    const int h = blockIdx.y;
    const int tid = threadIdx.x;
    const int lane = tid & 31;
    const int w = tid >> 5;

    const size_t kBase = (size_t)(i/kDiv)*kOuter + (size_t)(i%kDiv);

    for (int idx = tid; idx < Lk*64; idx += 128) {
        int tk = idx >> 6, d = idx & 63;
        size_t grow = (kBase + (size_t)tk*kStride)*D + h*DK + d;
        Ks[tk*65+d] = K[grow];
        Vs[tk*65+d] = V[grow];
    }
    __syncthreads();

    const int qb = (i/qDiv) * Lq;
    const int nj = (Lk + 31) >> 5;

    for (int tq = w; tq < Lq; tq += 4) {
        size_t qoff = (size_t)(qb + tq)*D + h*DK;
        qs[w*64 + lane]      = Q[qoff + lane];
        qs[w*64 + lane + 32] = Q[qoff + lane + 32];
        __syncwarp();

        float sc[4];
        #pragma unroll
        for (int j=0;j<4;j++) sc[j] = -INFINITY;

        for (int j=0;j<nj;j++) {
            int k = lane + (j<<5);
            if (k < Lk) {
                float dot = 0.f;
                const float* kr = Ks + k*65;
                const float* qq = qs + w*64;
                #pragma unroll
                for (int d=0; d<64; d++) dot += qq[d]*kr[d];
                dot *= scale;
                if (maskMode == 1) {
                    if (mask[(size_t)(i/maskDiv)*Lk + k] == 0) dot = -1e9f;
                } else if (maskMode == 2) {
                    if (mask[((size_t)i*Lq + tq)*Lk + k] == 0) dot = -1e9f;
                }
                sc[j] = dot;
            }
        }
        float mx = -INFINITY;
        for (int j=0;j<nj;j++) mx = fmaxf(mx, sc[j]);
        #pragma unroll
        for (int o=16;o>0;o>>=1) mx = fmaxf(mx, __shfl_xor_sync(0xffffffffu, mx, o));

        float e[4]; float sum = 0.f;
        for (int j=0;j<nj;j++) {
            e[j] = (sc[j] == -INFINITY) ? 0.f : __expf(sc[j] - mx);
            sum += e[j];
        }
        #pragma unroll
        for (int o=16;o>0;o>>=1) sum += __shfl_xor_sync(0xffffffffu, sum, o);
        const float inv = 1.f / sum;
        for (int j=0;j<nj;j++) {
            int k = lane + (j<<5);
            if (k < Lk) ps[w*Lk + k] = e[j] * inv;
        }
        __syncwarp();

        float o0 = 0.f, o1 = 0.f;
        for (int k=0;k<Lk;k++) {
            float p = ps[w*Lk + k];
            o0 += p * Vs[k*65 + lane];
            o1 += p * Vs[k*65 + lane + 32];
        }
        size_t orow = ((size_t)i*Lq + tq)*D + h*DK;
        O[orow + lane]      = o0;
        O[orow + lane + 32] = o1;
        __syncwarp();
    }
}

static void launch_attn(cudaStream_t st,
                        const float* Q, const float* K, const float* V, float* O,
                        const int* mask, int maskMode, int maskDiv,
                        int nb, int Lq, int Lk,
                        int qDiv, int kOuter, int kDiv, int kStride)
{
    dim3 grid(nb, NH);
    size_t smem = (size_t)(2*Lk*65 + 4*64 + 4*Lk) * sizeof(float);
    attn_kernel<<<grid, 128, smem, st>>>(Q, K, V, O, mask, maskMode, maskDiv,
                                         Lq, Lk, qDiv, kOuter, kDiv, kStride, 0.125f);
}

// ---------------- fold attention ----------------
__global__ void fold_attn_kernel(const float* __restrict__ O,
                                 const float* __restrict__ Qo,
                                 const float* __restrict__ sb,
                                 const int* __restrict__ mask, int maskApply,
                                 float* __restrict__ ctx, int Lk)
{
    extern __shared__ float sm[];
    float* Os = sm;
    float* sc = Os + Lk*512;
    float* pp = sc + 512;

    const int u = blockIdx.x;
    const int tid = threadIdx.x;
    const int h = tid >> 5;
    const int lane = tid & 31;
    const size_t base = (size_t)(u >> 6) * Lk * 64 + (u & 63);

    for (int idx = tid; idx < Lk*512; idx += 256) {
        int s = idx >> 9, d = idx & 511;
        Os[idx] = O[(base + (size_t)s*64)*D + d];
    }
    __syncthreads();

    float qreg[16];
    #pragma unroll
    for (int i=0;i<16;i++) qreg[i] = Qo[(size_t)u*(NH*D) + h*D + i*32 + lane];

    const float sbase = sb[u*NH + h];

    for (int s = 0; s < Lk; s++) {
        float dot = 0.f;
        const float* row = Os + s*512;
        #pragma unroll
        for (int i=0;i<16;i++) dot += qreg[i] * row[i*32 + lane];
        #pragma unroll
        for (int o=16;o>0;o>>=1) dot += __shfl_xor_sync(0xffffffffu, dot, o);
        float score = (sbase + dot) * 0.125f;
        if (maskApply && mask[(u>>6)*Lk + s] == 0) score = -1e9f;
        if (lane == 0) sc[h*64 + s] = score;
    }
    __syncwarp();

    float v0 = (lane      < Lk) ? sc[h*64 + lane]      : -INFINITY;
    float v1 = (lane + 32 < Lk) ? sc[h*64 + lane + 32] : -INFINITY;
    float mx = fmaxf(v0, v1);
    #pragma unroll
    for (int o=16;o>0;o>>=1) mx = fmaxf(mx, __shfl_xor_sync(0xffffffffu, mx, o));
    float e0 = (lane      < Lk) ? __expf(v0 - mx) : 0.f;
    float e1 = (lane + 32 < Lk) ? __expf(v1 - mx) : 0.f;
    float sum = e0 + e1;
    #pragma unroll
    for (int o=16;o>0;o>>=1) sum += __shfl_xor_sync(0xffffffffu, sum, o);
    const float inv = 1.f / sum;
    if (lane      < Lk) pp[h*64 + lane]      = e0 * inv;
    if (lane + 32 < Lk) pp[h*64 + lane + 32] = e1 * inv;
    __syncwarp();

    #pragma unroll
    for (int i=0;i<16;i++) {
        float acc = 0.f;
        for (int s=0;s<Lk;s++)
            acc += pp[h*64 + s] * Os[s*512 + i*32 + lane];
        ctx[(size_t)u*(NH*D) + h*D + i*32 + lane] = acc;
    }
}

// ---------------- small helpers ----------------
__global__ void transpose512(const float* __restrict__ in, float* __restrict__ out)
{
    __shared__ float t[32][33];
    int bx = blockIdx.x*32, by = blockIdx.y*32;
    for (int j = threadIdx.y; j < 32; j += 8)
        t[j][threadIdx.x] = in[(size_t)(by+j)*D + bx + threadIdx.x];
    __syncthreads();
    for (int j = threadIdx.y; j < 32; j += 8)
        out[(size_t)(bx+j)*D + by + threadIdx.x] = t[threadIdx.x][j];
}

__global__ void addrow_kernel(const float* __restrict__ a, const float* __restrict__ bvec,
                              float* __restrict__ c)
{
    int u = blockIdx.x, d = threadIdx.x;
    c[(size_t)u*D + d] = a[(size_t)u*D + d] + bvec[d];
}

__global__ void sbase_kernel(const float* __restrict__ Qp, const float* __restrict__ mmk,
                             float* __restrict__ sb)
{
    int u = blockIdx.x;
    int h = threadIdx.x >> 5, lane = threadIdx.x & 31;
    const float* q = Qp  + (size_t)u*D + h*64;
    const float* m = mmk + (size_t)u*D + h*64;
    float s = q[lane]*m[lane] + q[lane+32]*m[lane+32];
    #pragma unroll
    for (int o=16;o>0;o>>=1) s += __shfl_xor_sync(0xffffffffu, s, o);
    if (lane == 0) sb[u*NH + h] = s;
}

__global__ void add_kernel(const float* __restrict__ a, const float* __restrict__ b,
                           float* __restrict__ c, int n)
{
    int i = blockIdx.x*256 + threadIdx.x;
    if (i < n) c[i] = a[i] + b[i];
}

// ---------------- persistent stream/event resources ----------------
static cudaStream_t g_s2 = nullptr, g_s3 = nullptr;
static cudaEvent_t  g_evStart = nullptr, g_evEnc = nullptr, g_evA = nullptr,
                    g_evRound = nullptr, g_evFork = nullptr, g_evJoin = nullptr;

// ---------------- driver ----------------
extern "C" void kernel_launch(void* const* d_in, const int* in_sizes, int n_in,
                              void* d_out, int out_size)
{
    const float* x        = (const float*)d_in[0];
    const float* vft      = (const float*)d_in[1];
    const float* enc_his  = (const float*)d_in[2];
    const float* enc_cap  = (const float*)d_in[3];
    const float* enc_qry  = (const float*)d_in[4];
    const int*   trg_mask = (const int*)  d_in[5];
    const int*   his_mask = (const int*)  d_in[6];
    const int*   cap_mask = (const int*)  d_in[7];
    const int*   qry_mask = (const int*)  d_in[8];
    const int*   tmp_mask = (const int*)  d_in[9];
    const float* attn_w   = (const float*)d_in[10];
    const float* attn_b   = (const float*)d_in[11];
    const float* ff_w1    = (const float*)d_in[12];
    const float* ff_b1    = (const float*)d_in[13];
    const float* ff_w2    = (const float*)d_in[14];
    const float* ff_b2    = (const float*)d_in[15];
    const float* ln_g     = (const float*)d_in[16];
    const float* ln_b     = (const float*)d_in[17];
    float* outp = (float*)d_out;

    if (!g_s2) {
        cudaStreamCreateWithFlags(&g_s2, cudaStreamNonBlocking);
        cudaStreamCreateWithFlags(&g_s3, cudaStreamNonBlocking);
        cudaEventCreateWithFlags(&g_evStart, cudaEventDisableTiming);
        cudaEventCreateWithFlags(&g_evEnc,  cudaEventDisableTiming);
        cudaEventCreateWithFlags(&g_evA,    cudaEventDisableTiming);
        cudaEventCreateWithFlags(&g_evRound,cudaEventDisableTiming);
        cudaEventCreateWithFlags(&g_evFork, cudaEventDisableTiming);
        cudaEventCreateWithFlags(&g_evJoin, cudaEventDisableTiming);
    }
    cudaStream_t s0 = 0, s2 = g_s2, s3 = g_s3;

    float *bigKV,*big2,*qkv,*kvEnc,*lnb,*ob,*cur,*ts,*mid,*mmb,*mmkv,*sb,*qo,*ctx,*w12,*w1t;
    float *bigKV2,*big3,*lnB,*qB,*oB,*st,*midB,*mmbB,*mmkvB,*sbB,*qoB,*ctxB,*w12B,*w1tB;
    __nv_bfloat16 *vftH,*wH;
    cudaGetSymbolAddress((void**)&bigKV, g_bigKV);
    cudaGetSymbolAddress((void**)&big2,  g_big2);
    cudaGetSymbolAddress((void**)&qkv,   g_qkv);
    cudaGetSymbolAddress((void**)&kvEnc, g_kvEnc);
    cudaGetSymbolAddress((void**)&lnb,   g_ln);
    cudaGetSymbolAddress((void**)&ob,    g_o);
    cudaGetSymbolAddress((void**)&cur,   g_cur);
    cudaGetSymbolAddress((void**)&ts,    g_ts);
    cudaGetSymbolAddress((void**)&mid,   g_mid);
    cudaGetSymbolAddress((void**)&mmb,   g_mmb);
    cudaGetSymbolAddress((void**)&mmkv,  g_mmkv);
    cudaGetSymbolAddress((void**)&sb,    g_sb);
    cudaGetSymbolAddress((void**)&qo,    g_qo);
    cudaGetSymbolAddress((void**)&ctx,   g_ctx);
    cudaGetSymbolAddress((void**)&w12,   g_w12);
    cudaGetSymbolAddress((void**)&w1t,   g_w1t);
    cudaGetSymbolAddress((void**)&bigKV2,g_bigKV2);
    cudaGetSymbolAddress((void**)&big3,  g_big3);
    cudaGetSymbolAddress((void**)&lnB,   g_lnB);
    cudaGetSymbolAddress((void**)&qB,    g_qB);
    cudaGetSymbolAddress((void**)&oB,    g_oB);
    cudaGetSymbolAddress((void**)&st,    g_st);
    cudaGetSymbolAddress((void**)&midB,  g_midB);
    cudaGetSymbolAddress((void**)&mmbB,  g_mmbB);
    cudaGetSymbolAddress((void**)&mmkvB, g_mmkvB);
    cudaGetSymbolAddress((void**)&sbB,   g_sbB);
    cudaGetSymbolAddress((void**)&qoB,   g_qoB);
    cudaGetSymbolAddress((void**)&ctxB,  g_ctxB);
    cudaGetSymbolAddress((void**)&w12B,  g_w12B);
    cudaGetSymbolAddress((void**)&w1tB,  g_w1tB);
    cudaGetSymbolAddress((void**)&vftH,  g_vftH);
    cudaGetSymbolAddress((void**)&wH,    g_wH);

    float* qb = qkv;
    float* kb = qkv + (size_t)2048*D;
    float* vb = qkv + (size_t)4096*D;
    float* kHis = kvEnc;
    float* kCap = kvEnc + (size_t)4096*D;
    float* kQry = kvEnc + (size_t)6144*D;
    float* big0 = bigKV;
    float* big1 = bigKV + (size_t)NV*D;
    float* big0B = bigKV2;
    float* big1B = bigKV2 + (size_t)NV*D;
    float* mmk = mmkv;
    float* mmv = mmkv + (size_t)NT*D;
    float* mmkB = mmkvB;
    float* mmvB = mmkvB + (size_t)NT*D;
    float* w1 = w12;
    float* w2 = w12 + (size_t)D*D;
    float* w1B = w12B;
    float* w2B = w12B + (size_t)D*D;
    __nv_bfloat16* wH45 = wH;                      // bf16 W(4,1),W(4,2)
    __nv_bfloat16* wH67 = wH + (size_t)2*D*D;      // bf16 W(6,1),W(6,2)

    cudaFuncSetAttribute(attn_kernel, cudaFuncAttributeMaxDynamicSharedMemorySize, 73728);
    cudaFuncSetAttribute(fold_attn_kernel, cudaFuncAttributeMaxDynamicSharedMemorySize, 64*512*4 + 4096);
    cudaFuncSetAttribute(bf16_gemm_big_b, cudaFuncAttributeMaxDynamicSharedMemorySize, HSMEM);

    #define WATT(l,j) (attn_w + ((size_t)(l)*4+(j))*D*D)
    #define BATT(l,j) (attn_b + ((size_t)(l)*4+(j))*D)
    const long ZW = (long)D*D;
    const long ZB = D;
    const long ZKV = (long)2048*D;

    // ======== PRELUDE ========
    cudaEventRecord(g_evStart, s0);
    cudaStreamWaitEvent(s2, g_evStart, 0);
    cudaStreamWaitEvent(s3, g_evStart, 0);

    // s3: round vft + both weight pairs to bf16 -> evRound, then K6/V6 (bf16)
    {
        long n4 = (long)NV*D/4;
        round_bf16_kernel<<<(unsigned)((n4+255)/256),256,0,s3>>>(vft, vftH, n4);
        long w4 = (long)2*D*D/4;
        round_bf16_kernel<<<(unsigned)((w4+255)/256),256,0,s3>>>(WATT(4,1), wH45, w4);
        round_bf16_kernel<<<(unsigned)((w4+255)/256),256,0,s3>>>(WATT(6,1), wH67, w4);
        cudaEventRecord(g_evRound, s3);
    }
    gemmH(s3, vftH,D,0, wH67,D,ZW, BATT(6,1),ZB, nullptr,0,0,0, big0B,D,(long)NV*D, NV,D,D, 2); // K6,V6
    gemmS(s3, WATT(6,3),D,0, WATT(7,1),D,ZW, nullptr,0, nullptr,0,0,0, w1B,D,(long)D*D, D,D,D, 2);
    transpose512<<<dim3(16,16),dim3(32,8),0,s3>>>(w1B, w1tB);

    // s2: encoder K/V -> evEnc; then K4/V4 (bf16) + fold-5 weight products -> evA
    gemmS(s2, enc_his,D,0, WATT(1,1),D,ZW, BATT(1,1),ZB, nullptr,0,0,0, kHis,D,(long)2048*D, 2048,D,D, 2);
    gemmS(s2, enc_cap,D,0, WATT(2,1),D,ZW, BATT(2,1),ZB, nullptr,0,0,0, kCap,D,(long)1024*D, 1024,D,D, 2);
    gemmS(s2, enc_qry,D,0, WATT(3,1),D,ZW, BATT(3,1),ZB, nullptr,0,0,0, kQry,D,(long)512*D,  512,D,D, 2);
    cudaEventRecord(g_evEnc, s2);
    cudaStreamWaitEvent(s2, g_evRound, 0);
    gemmH(s2, vftH,D,0, wH45,D,ZW, BATT(4,1),ZB, nullptr,0,0,0, big0,D,(long)NV*D, NV,D,D, 2);  // K4,V4
    gemmS(s2, WATT(4,3),D,0, WATT(5,1),D,ZW, nullptr,0, nullptr,0,0,0, w1,D,(long)D*D, D,D,D, 2);
    transpose512<<<dim3(16,16),dim3(32,8),0,s2>>>(w1, w1t);
    cudaEventRecord(g_evA, s2);

    // ===== MHA0 (s0) =====
    ln_kernel<<<NT,256,0,s0>>>(x, ln_g + 0*D, ln_b + 0*D, lnb);
    gemmS(s0, lnb,D,0, WATT(0,0),D,ZW, BATT(0,0),ZB, nullptr,0,0,0, qb,D,ZKV, NT,D,D, 3);
    launch_attn(s0, qb, kb, vb, ob, trg_mask, 2, 1, BSZ, TTRG, TTRG, 1, TTRG, 1, 1);
    gemm1(s0, ob,D, WATT(0,3),D, BATT(0,3), x,D,0, cur,D, NT, D, D);

    cudaStreamWaitEvent(s0, g_evEnc, 0);

    // ===== MHA1 =====
    ln_kernel<<<NT,256,0,s0>>>(cur, ln_g + 1*D, ln_b + 1*D, lnb);
    gemm1(s0, lnb,D, WATT(1,0),D, BATT(1,0), nullptr,0,0, qb,D, NT, D, D);
    launch_attn(s0, qb, kHis, kHis + (size_t)2048*D, ob, his_mask, 1, 1, BSZ, TTRG, 128, 1, 128, 1, 1);
    gemm1(s0, ob,D, WATT(1,3),D, BATT(1,3), cur,D,0, cur,D, NT, D, D);

    // ===== MHA2 =====
    ln_kernel<<<NT,256,0,s0>>>(cur, ln_g + 2*D, ln_b + 2*D, lnb);
    gemm1(s0, lnb,D, WATT(2,0),D, BATT(2,0), nullptr,0,0, qb,D, NT, D, D);
    launch_attn(s0, qb, kCap, kCap + (size_t)1024*D, ob, cap_mask, 1, 1, BSZ, TTRG, 64, 1, 64, 1, 1);
    gemm1(s0, ob,D, WATT(2,3),D, BATT(2,3), cur,D,0, cur,D, NT, D, D);

    // ===== MHA3 -> mm (cur) =====
    ln_kernel<<<NT,256,0,s0>>>(cur, ln_g + 3*D, ln_b + 3*D, lnb);
    gemm1(s0, lnb,D, WATT(3,0),D, BATT(3,0), nullptr,0,0, qb,D, NT, D, D);
    launch_attn(s0, qb, kQry, kQry + (size_t)512*D, ob, qry_mask, 1, 1, BSZ, TTRG, 32, 1, 32, 1, 1);
    gemm1(s0, ob,D, WATT(3,3),D, BATT(3,3), cur,D,0, cur,D, NT, D, D);
    // cur == mm

    // ======== FORK: branch B on s3 ========
    cudaEventRecord(g_evFork, s0);
    cudaStreamWaitEvent(s3, g_evFork, 0);

    // ---- Branch B: MHA6 ----
    ln_kernel<<<NT,256,0,s3>>>(cur, ln_g + 7*D, ln_b + 7*D, lnB);
    gemm1(s3, lnB,D, WATT(6,0),D, BATT(6,0), nullptr,0,0, qB,D, NT, D, D);
    launch_attn(s3, qB, big0B, big1B, big3, nullptr, 0, 1,
                BSZ*TT, TTRG, SSP, TT, SSP, 1, 1);                               // O6
    // ---- Branch B: MHA7 folded ----
    {
        const float* bo = BATT(6,3);
        addrow_kernel<<<NT,512,0,s3>>>(cur, bo, mmbB);
        gemmS(s3, mmbB,D,0, WATT(7,1),D,ZW, BATT(7,1),ZB, nullptr,0,0,0, mmkB,D,(long)NT*D, NT,D,D, 2);
        ln_kernel<<<NT,256,0,s3>>>(cur, ln_g + 8*D, ln_b + 8*D, lnB);
        gemm1(s3, lnB,D, WATT(7,0),D, BATT(7,0), nullptr,0,0, qB,D, NT, D, D);
        gemmS(s3, qB,D,64, w1tB,D,(long)64*D, nullptr,0, nullptr,0,0,0, qoB,NH*D,(long)D, NT,D,64, 8);
        sbase_kernel<<<NT,256,0,s3>>>(qB, mmkB, sbB);
        fold_attn_kernel<<<NT,256, TT*512*4 + 4096, s3>>>(big3, qoB, sbB, tmp_mask, 1, ctxB, TT);
        gemmS(s3, ctxB,NH*D,(long)D, w2B,D,64, nullptr,0, mmvB,D,64,0, oB,D,64, NT,64,D, 8);
        gemm1(s3, oB,D, WATT(7,3),D, BATT(7,3), cur,D,0, st,D, NT, D, D);
    }
    // ---- Branch B: FFN1 ----
    ln_kernel<<<NT,256,0,s3>>>(st, ln_g + 9*D, ln_b + 9*D, lnB);
    gemm1(s3, lnB,D, ff_w1 + 1*(size_t)D*DFF,DFF, ff_b1 + 1*DFF, nullptr,0,1, midB,DFF, NT, DFF, D);
    gemm1(s3, midB,DFF, ff_w2 + 1*(size_t)DFF*D,D, ff_b2 + 1*D, st,D,0, st,D, NT, D, DFF);
    cudaEventRecord(g_evJoin, s3);

    // ======== Branch A on s0 ========
    cudaStreamWaitEvent(s0, g_evA, 0);
    ln_kernel<<<NT,256,0,s0>>>(cur, ln_g + 4*D, ln_b + 4*D, lnb);
    gemm1(s0, lnb,D, WATT(4,0),D, BATT(4,0), nullptr,0,0, qb,D, NT, D, D);
    launch_attn(s0, qb, big0, big1, big2, tmp_mask, 1, SSP,
                BSZ*SSP, TTRG, TT, SSP, TT*SSP, SSP, SSP);                       // O4
    // ---- MHA5 folded ----
    {
        const float* bo = BATT(4,3);
        addrow_kernel<<<NT,512,0,s0>>>(cur, bo, mmb);
        gemmS(s0, mmb,D,0, WATT(5,1),D,ZW, BATT(5,1),ZB, nullptr,0,0,0, mmk,D,(long)NT*D, NT,D,D, 2);
        ln_kernel<<<NT,256,0,s0>>>(cur, ln_g + 5*D, ln_b + 5*D, lnb);
        gemm1(s0, lnb,D, WATT(5,0),D, BATT(5,0), nullptr,0,0, qb,D, NT, D, D);
        gemmS(s0, qb,D,64, w1t,D,(long)64*D, nullptr,0, nullptr,0,0,0, qo,NH*D,(long)D, NT,D,64, 8);
        sbase_kernel<<<NT,256,0,s0>>>(qb, mmk, sb);
        fold_attn_kernel<<<NT,256, SSP*512*4 + 4096, s0>>>(big2, qo, sb, nullptr, 0, ctx, SSP);
        gemmS(s0, ctx,NH*D,(long)D, w2,D,64, nullptr,0, mmv,D,64,0, ob,D,64, NT,64,D, 8);
        gemm1(s0, ob,D, WATT(5,3),D, BATT(5,3), cur,D,0, ts,D, NT, D, D);
    }
    // ---- FFN0 ----
    ln_kernel<<<NT,256,0,s0>>>(ts, ln_g + 6*D, ln_b + 6*D, lnb);
    gemm1(s0, lnb,D, ff_w1 + 0*(size_t)D*DFF,DFF, ff_b1 + 0*DFF, nullptr,0,1, mid,DFF, NT, DFF, D);
    gemm1(s0, mid,DFF, ff_w2 + 0*(size_t)DFF*D,D, ff_b2 + 0*D, ts,D,0, ts,D, NT, D, DFF);

    // ======== JOIN ========
    cudaStreamWaitEvent(s0, g_evJoin, 0);

    // ===== out = ts + st; FFN2 =====
    add_kernel<<<(NT*D+255)/256,256,0,s0>>>(ts, st, qb, NT*D);
    ln_kernel<<<NT,256,0,s0>>>(qb, ln_g + 10*D, ln_b + 10*D, lnb);
    gemm1(s0, lnb,D, ff_w1 + 2*(size_t)D*DFF,DFF, ff_b1 + 2*DFF, nullptr,0,1, mid,DFF, NT, DFF, D);
    gemm1(s0, mid,DFF, ff_w2 + 2*(size_t)DFF*D,D, ff_b2 + 2*D, qb,D,0, outp,D, NT, D, DFF);
}